// round 11
// baseline (speedup 1.0000x reference)
#include <cuda_runtime.h>
#include <math.h>
#include <stdint.h>

#define NTOK 1569
#define BATCH 8
#define CDIM 768
#define NHEAD 12
#define HDIM 64
#define BH (BATCH*NHEAD)            /* 96 */
#define BHND (BH*NTOK*HDIM)         /* 9639936 */
#define NBC (NTOK*BATCH*CDIM)       /* 9639936 */

// ---------------- scratch (device globals: no allocation allowed) ----------
__device__ float g_q[BHND];
__device__ float g_k[BHND];
__device__ float g_v[BHND];
__device__ float g_xs[BHND];
__device__ float g_t1[BHND];
__device__ float g_acc[BHND];
__device__ float g_xr[NBC];               // tf32-rounded x
__device__ float g_wq[3*CDIM*CDIM];       // tf32-rounded Wqkv
__device__ float g_wp[CDIM*CDIM];         // tf32-rounded Wproj
__device__ float g_rownorm[BATCH*NTOK];
__device__ float g_invtemp[BATCH];

// ---------------- helpers ---------------------------------------------------
__device__ __forceinline__ float to_tf32(float x) {
    uint32_t u;
    asm("cvt.rna.tf32.f32 %0, %1;" : "=r"(u) : "f"(x));
    return __uint_as_float(u);
}

__device__ __forceinline__ float ex2(float x) {
    float r;
    asm("ex2.approx.f32 %0, %1;" : "=f"(r) : "f"(x));
    return r;
}

__device__ __forceinline__ void mma8(float* c, uint32_t a0, uint32_t a1,
                                     uint32_t a2, uint32_t a3,
                                     uint32_t b0, uint32_t b1) {
    asm volatile(
        "mma.sync.aligned.m16n8k8.row.col.f32.tf32.tf32.f32 "
        "{%0,%1,%2,%3}, {%4,%5,%6,%7}, {%8,%9}, {%0,%1,%2,%3};"
        : "+f"(c[0]), "+f"(c[1]), "+f"(c[2]), "+f"(c[3])
        : "r"(a0), "r"(a1), "r"(a2), "r"(a3), "r"(b0), "r"(b1));
}

__device__ __forceinline__ uint32_t smem_u32(const void* p) {
    return (uint32_t)__cvta_generic_to_shared(p);
}
__device__ __forceinline__ void cp16(uint32_t dst, const void* src, bool pred) {
    int sz = pred ? 16 : 0;
    asm volatile("cp.async.ca.shared.global [%0], [%1], 16, %2;\n"
                 :: "r"(dst), "l"(src), "r"(sz));
}
__device__ __forceinline__ void cp_commit() {
    asm volatile("cp.async.commit_group;\n");
}
__device__ __forceinline__ void cp_wait1() {
    asm volatile("cp.async.wait_group 1;\n");
}
__device__ __forceinline__ void cp_wait0() {
    asm volatile("cp.async.wait_group 0;\n");
}

// ---------------- round fp32 -> tf32 (element-wise) -------------------------
__global__ void round_kernel(const float* __restrict__ in, float* __restrict__ out,
                             int n4) {
    int i = blockIdx.x * blockDim.x + threadIdx.x;
    if (i < n4) {
        float4 v = ((const float4*)in)[i];
        v.x = to_tf32(v.x); v.y = to_tf32(v.y);
        v.z = to_tf32(v.z); v.w = to_tf32(v.w);
        ((float4*)out)[i] = v;
    }
}

// ---------------- per-token L2 norm over C (for inv_temp) ------------------
__global__ void rownorm_kernel(const float* __restrict__ x) {
    int r = (blockIdx.x * blockDim.x + threadIdx.x) >> 5;
    int lane = threadIdx.x & 31;
    if (r >= BATCH * NTOK) return;
    int b = r / NTOK, n = r - b * NTOK;
    const float* p = x + (size_t)n * (BATCH * CDIM) + b * CDIM;
    float ss = 0.f;
#pragma unroll
    for (int kblk = 0; kblk < 6; kblk++) {
        float4 v = *(const float4*)(p + kblk * 128 + lane * 4);
        ss += v.x * v.x + v.y * v.y + v.z * v.z + v.w * v.w;
    }
#pragma unroll
    for (int o = 16; o; o >>= 1) ss += __shfl_xor_sync(0xffffffffu, ss, o);
    if (lane == 0) g_rownorm[r] = sqrtf(ss);
}

__global__ void invtemp_kernel() {
    __shared__ float sh[256];
    int b = blockIdx.x;
    float s = 0.f;
    for (int n = threadIdx.x; n < NTOK; n += 256) s += g_rownorm[b * NTOK + n];
    sh[threadIdx.x] = s;
    __syncthreads();
    for (int o = 128; o; o >>= 1) {
        if (threadIdx.x < o) sh[threadIdx.x] += sh[threadIdx.x + o];
        __syncthreads();
    }
    if (threadIdx.x == 0) g_invtemp[b] = (sh[0] / (float)NTOK) * 0.125f;
}

// ---------------- l2 normalize last dim (hd=64), tf32-rounded output --------
__global__ void l2norm_kernel(const float* __restrict__ in, float* __restrict__ out) {
    int r = (blockIdx.x * blockDim.x + threadIdx.x) >> 5;
    int lane = threadIdx.x & 31;
    if (r >= BH * NTOK) return;
    float2 v = *(const float2*)(in + (size_t)r * HDIM + lane * 2);
    float ss = v.x * v.x + v.y * v.y;
#pragma unroll
    for (int o = 16; o; o >>= 1) ss += __shfl_xor_sync(0xffffffffu, ss, o);
    float inv = 1.f / fmaxf(sqrtf(ss), 1e-12f);
    *(float2*)(out + (size_t)r * HDIM + lane * 2) =
        make_float2(to_tf32(v.x * inv), to_tf32(v.y * inv));
}

// ---------------- elementwise accumulate (tf32-rounded output) --------------
__global__ void add_kernel(float* __restrict__ a, const float* __restrict__ b) {
    int i = blockIdx.x * blockDim.x + threadIdx.x;
    if (i < BHND / 4) {
        float4 xa = ((float4*)a)[i];
        float4 xb = ((const float4*)b)[i];
        xa.x = to_tf32(xa.x + xb.x); xa.y = to_tf32(xa.y + xb.y);
        xa.z = to_tf32(xa.z + xb.z); xa.w = to_tf32(xa.w + xb.w);
        ((float4*)a)[i] = xa;
    }
}

// ---------------- flash attention (tf32 TC, cp.async double-buffer) ---------
// Block: 128 thr (4 warps). CTA Q-tile 128 rows; each warp 32 rows as two m16
// blocks sharing K/V fragments. K/V tiles stream via cp.async into 2 buffers.
// All gmem operands are pre-rounded to tf32 at their producers.
// Strides: Q/P/K = 68 (bank 4g+t perm), V = 72 (bank 8t+g perm).
#define AST 68
#define VST 72
#define NT_TILES ((NTOK + 63) / 64)    /* 25 */
#define ATT_SMEM ((128*AST + 2*64*AST + 2*64*VST) * 4)

__global__ __launch_bounds__(128) void attn_tc(
    const float* __restrict__ Q, const float* __restrict__ K,
    const float* __restrict__ V, float* __restrict__ O,
    int useInvTemp, float cscale, int roundOut) {
    extern __shared__ float sm[];
    float* Ps = sm;                         // 128 x AST: Q staging, then P
    float* Kb[2] = { sm + 128 * AST, sm + 128 * AST + 64 * AST };
    float* Vb[2] = { sm + 128 * AST + 2 * 64 * AST,
                     sm + 128 * AST + 2 * 64 * AST + 64 * VST };

    int tid = threadIdx.x;
    int warp = tid >> 5, lane = tid & 31;
    int g = lane >> 2, t = lane & 3;
    int bh = blockIdx.y;
    int m0 = blockIdx.x * 128;
    float scale = useInvTemp ? g_invtemp[bh / NHEAD] : cscale;
    const float qscale = scale * 1.4426950408889634f;  // fold log2(e) for ex2
    const size_t base = (size_t)bh * NTOK * HDIM;
    const int rA = warp * 32 + g;
    const int rB = warp * 32 + 16 + g;

    // ---- kick off K/V tile 0 loads ----
    {
#pragma unroll
        for (int e = 0; e < 8; e++) {
            int idx = tid + e * 128;
            int row = idx >> 4;
            int d = (idx & 15) << 2;
            bool p = row < NTOK;   // kt0 = 0
            cp16(smem_u32(&Kb[0][row * AST + d]), K + base + (size_t)row * HDIM + d, p);
            cp16(smem_u32(&Vb[0][row * VST + d]), V + base + (size_t)row * HDIM + d, p);
        }
        cp_commit();
    }

    // ---- stage Q (scaled, rounded) into Ps ----
#pragma unroll
    for (int e = 0; e < 16; e++) {
        int idx = tid + e * 128;
        int row = idx >> 4;
        int d = (idx & 15) << 2;
        float4 qv = make_float4(0.f, 0.f, 0.f, 0.f);
        if (m0 + row < NTOK)
            qv = *(const float4*)(Q + base + (size_t)(m0 + row) * HDIM + d);
        float4 w;
        w.x = to_tf32(qv.x * qscale); w.y = to_tf32(qv.y * qscale);
        w.z = to_tf32(qv.z * qscale); w.w = to_tf32(qv.w * qscale);
        *(float4*)&Ps[row * AST + d] = w;
    }
    __syncthreads();

    // ---- hoist Q fragments for both m-blocks into registers ----
    uint32_t qA[8][4], qB[8][4];
    {
        const uint32_t* pu = (const uint32_t*)Ps;
#pragma unroll
        for (int kt = 0; kt < 8; kt++) {
            qA[kt][0] = pu[rA * AST + kt * 8 + t];
            qA[kt][1] = pu[(rA + 8) * AST + kt * 8 + t];
            qA[kt][2] = pu[rA * AST + kt * 8 + t + 4];
            qA[kt][3] = pu[(rA + 8) * AST + kt * 8 + t + 4];
            qB[kt][0] = pu[rB * AST + kt * 8 + t];
            qB[kt][1] = pu[(rB + 8) * AST + kt * 8 + t];
            qB[kt][2] = pu[rB * AST + kt * 8 + t + 4];
            qB[kt][3] = pu[(rB + 8) * AST + kt * 8 + t + 4];
        }
    }
    __syncthreads();   // Ps reads done before softmax overwrites

    float lA0 = 0.f, lA1 = 0.f, lB0 = 0.f, lB1 = 0.f;
    float oA[8][4], oB[8][4];
#pragma unroll
    for (int nt = 0; nt < 8; nt++)
#pragma unroll
        for (int j = 0; j < 4; j++) { oA[nt][j] = 0.f; oB[nt][j] = 0.f; }

    for (int i = 0; i < NT_TILES; i++) {
        int cur = i & 1;
        int kt0 = i * 64;
        // issue next tile into the other buffer (its readers finished at the
        // __syncthreads ending iteration i-1)
        if (i + 1 < NT_TILES) {
            int nkt0 = kt0 + 64;
#pragma unroll
            for (int e = 0; e < 8; e++) {
                int idx = tid + e * 128;
                int row = idx >> 4;
                int d = (idx & 15) << 2;
                bool p = (nkt0 + row) < NTOK;
                int rr = p ? (nkt0 + row) : (NTOK - 1);
                cp16(smem_u32(&Kb[1 - cur][row * AST + d]),
                     K + base + (size_t)rr * HDIM + d, p);
                cp16(smem_u32(&Vb[1 - cur][row * VST + d]),
                     V + base + (size_t)rr * HDIM + d, p);
            }
            cp_commit();
            cp_wait1();
        } else {
            cp_wait0();
        }
        __syncthreads();   // tile i data visible to all warps

        const uint32_t* ku = (const uint32_t*)Kb[cur];
        const uint32_t* vu = (const uint32_t*)Vb[cur];

        // ---- S = (Q*qscale) K^T ----
        float sA[8][4], sB[8][4];
#pragma unroll
        for (int nt = 0; nt < 8; nt++)
#pragma unroll
            for (int j = 0; j < 4; j++) { sA[nt][j] = 0.f; sB[nt][j] = 0.f; }

#pragma unroll
        for (int kt = 0; kt < 8; kt++) {
#pragma unroll
            for (int nt = 0; nt < 8; nt++) {
                uint32_t b0 = ku[(nt * 8 + g) * AST + kt * 8 + t];
                uint32_t b1 = ku[(nt * 8 + g) * AST + kt * 8 + t + 4];
                mma8(sA[nt], qA[kt][0], qA[kt][1], qA[kt][2], qA[kt][3], b0, b1);
                mma8(sB[nt], qB[kt][0], qB[kt][1], qB[kt][2], qB[kt][3], b0, b1);
            }
        }

        // ---- no-max softmax: p = 2^s ----
        bool tail = (kt0 + 64 > NTOK);
#pragma unroll
        for (int nt = 0; nt < 8; nt++) {
            if (tail) {
                int cg = kt0 + nt * 8 + 2 * t;
                if (cg >= NTOK) {
                    sA[nt][0] = -1e30f; sA[nt][2] = -1e30f;
                    sB[nt][0] = -1e30f; sB[nt][2] = -1e30f;
                }
                if (cg + 1 >= NTOK) {
                    sA[nt][1] = -1e30f; sA[nt][3] = -1e30f;
                    sB[nt][1] = -1e30f; sB[nt][3] = -1e30f;
                }
            }
            float pA0 = ex2(sA[nt][0]);
            float pA1 = ex2(sA[nt][1]);
            float pA2 = ex2(sA[nt][2]);
            float pA3 = ex2(sA[nt][3]);
            float pB0 = ex2(sB[nt][0]);
            float pB1 = ex2(sB[nt][1]);
            float pB2 = ex2(sB[nt][2]);
            float pB3 = ex2(sB[nt][3]);
            lA0 += pA0 + pA1; lA1 += pA2 + pA3;
            lB0 += pB0 + pB1; lB1 += pB2 + pB3;
            int col = nt * 8 + 2 * t;
            *(float2*)&Ps[rA * AST + col]       = make_float2(to_tf32(pA0), to_tf32(pA1));
            *(float2*)&Ps[(rA + 8) * AST + col] = make_float2(to_tf32(pA2), to_tf32(pA3));
            *(float2*)&Ps[rB * AST + col]       = make_float2(to_tf32(pB0), to_tf32(pB1));
            *(float2*)&Ps[(rB + 8) * AST + col] = make_float2(to_tf32(pB2), to_tf32(pB3));
        }
        __syncwarp();

        // ---- O += P V ----
        const uint32_t* pu = (const uint32_t*)Ps;
#pragma unroll
        for (int kt = 0; kt < 8; kt++) {
            uint32_t aA0 = pu[rA * AST + kt * 8 + t];
            uint32_t aA1 = pu[(rA + 8) * AST + kt * 8 + t];
            uint32_t aA2 = pu[rA * AST + kt * 8 + t + 4];
            uint32_t aA3 = pu[(rA + 8) * AST + kt * 8 + t + 4];
            uint32_t aB0 = pu[rB * AST + kt * 8 + t];
            uint32_t aB1 = pu[(rB + 8) * AST + kt * 8 + t];
            uint32_t aB2 = pu[rB * AST + kt * 8 + t + 4];
            uint32_t aB3 = pu[(rB + 8) * AST + kt * 8 + t + 4];
#pragma unroll
            for (int nt = 0; nt < 8; nt++) {
                uint32_t b0 = vu[(kt * 8 + t) * VST + nt * 8 + g];
                uint32_t b1 = vu[(kt * 8 + t + 4) * VST + nt * 8 + g];
                mma8(oA[nt], aA0, aA1, aA2, aA3, b0, b1);
                mma8(oB[nt], aB0, aB1, aB2, aB3, b0, b1);
            }
        }
        __syncthreads();   // all warps done with buf[cur] before it is refilled
    }

    // deferred l reduction over the 4 t-lanes of each row group
    lA0 += __shfl_xor_sync(0xffffffffu, lA0, 1);
    lA0 += __shfl_xor_sync(0xffffffffu, lA0, 2);
    lA1 += __shfl_xor_sync(0xffffffffu, lA1, 1);
    lA1 += __shfl_xor_sync(0xffffffffu, lA1, 2);
    lB0 += __shfl_xor_sync(0xffffffffu, lB0, 1);
    lB0 += __shfl_xor_sync(0xffffffffu, lB0, 2);
    lB1 += __shfl_xor_sync(0xffffffffu, lB1, 1);
    lB1 += __shfl_xor_sync(0xffffffffu, lB1, 2);
    float iA0 = 1.f / lA0, iA1 = 1.f / lA1, iB0 = 1.f / lB0, iB1 = 1.f / lB1;
#pragma unroll
    for (int nt = 0; nt < 8; nt++) {
        int col = nt * 8 + 2 * t;
        int r;
        float v0, v1;
        r = m0 + rA;
        if (r < NTOK) {
            v0 = oA[nt][0] * iA0; v1 = oA[nt][1] * iA0;
            if (roundOut) { v0 = to_tf32(v0); v1 = to_tf32(v1); }
            *(float2*)(O + base + (size_t)r * HDIM + col) = make_float2(v0, v1);
        }
        r = m0 + rA + 8;
        if (r < NTOK) {
            v0 = oA[nt][2] * iA1; v1 = oA[nt][3] * iA1;
            if (roundOut) { v0 = to_tf32(v0); v1 = to_tf32(v1); }
            *(float2*)(O + base + (size_t)r * HDIM + col) = make_float2(v0, v1);
        }
        r = m0 + rB;
        if (r < NTOK) {
            v0 = oB[nt][0] * iB0; v1 = oB[nt][1] * iB0;
            if (roundOut) { v0 = to_tf32(v0); v1 = to_tf32(v1); }
            *(float2*)(O + base + (size_t)r * HDIM + col) = make_float2(v0, v1);
        }
        r = m0 + rB + 8;
        if (r < NTOK) {
            v0 = oB[nt][2] * iB1; v1 = oB[nt][3] * iB1;
            if (roundOut) { v0 = to_tf32(v0); v1 = to_tf32(v1); }
            *(float2*)(O + base + (size_t)r * HDIM + col) = make_float2(v0, v1);
        }
    }
}

// ---------------- qkv projection GEMM (tf32 TC, cp.async) -------------------
#define GST 36
#define KTILES (CDIM / 32)   /* 24 */

__global__ __launch_bounds__(128) void qkv_tc(const float* __restrict__ x,
                                              const float* __restrict__ W) {
    __shared__ float As[2][64 * GST];
    __shared__ float Bs[2][64 * GST];
    int tid = threadIdx.x;
    int warp = tid >> 5, lane = tid & 31;
    int g = lane >> 2, t = lane & 3;
    int m0 = blockIdx.x * 64;
    int o0 = blockIdx.y * 64;
    int b = blockIdx.z;
    const int r0 = warp * 16 + g;

    float c[8][4];
#pragma unroll
    for (int nt = 0; nt < 8; nt++)
#pragma unroll
        for (int j = 0; j < 4; j++) c[nt][j] = 0.f;

    // issue tile 0
#pragma unroll
    for (int e = 0; e < 4; e++) {
        int idx = tid + e * 128;
        int row = idx >> 3;
        int cs = (idx & 7) << 2;
        bool p = (m0 + row) < NTOK;
        int rr = p ? (m0 + row) : (NTOK - 1);
        cp16(smem_u32(&As[0][row * GST + cs]),
             x + (size_t)rr * (BATCH * CDIM) + b * CDIM + cs, p);
        cp16(smem_u32(&Bs[0][row * GST + cs]),
             W + (size_t)(o0 + row) * CDIM + cs, true);
    }
    cp_commit();

    for (int i = 0; i < KTILES; i++) {
        int cur = i & 1;
        if (i + 1 < KTILES) {
            int c0 = (i + 1) * 32;
#pragma unroll
            for (int e = 0; e < 4; e++) {
                int idx = tid + e * 128;
                int row = idx >> 3;
                int cs = (idx & 7) << 2;
                bool p = (m0 + row) < NTOK;
                int rr = p ? (m0 + row) : (NTOK - 1);
                cp16(smem_u32(&As[1 - cur][row * GST + cs]),
                     x + (size_t)rr * (BATCH * CDIM) + b * CDIM + c0 + cs, p);
                cp16(smem_u32(&Bs[1 - cur][row * GST + cs]),
                     W + (size_t)(o0 + row) * CDIM + c0 + cs, true);
            }
            cp_commit();
            cp_wait1();
        } else {
            cp_wait0();
        }
        __syncthreads();

        const uint32_t* au = (const uint32_t*)As[cur];
        const uint32_t* bu = (const uint32_t*)Bs[cur];
#pragma unroll
        for (int kt = 0; kt < 4; kt++) {
            uint32_t a0 = au[r0 * GST + kt * 8 + t];
            uint32_t a1 = au[(r0 + 8) * GST + kt * 8 + t];
            uint32_t a2 = au[r0 * GST + kt * 8 + t + 4];
            uint32_t a3 = au[(r0 + 8) * GST + kt * 8 + t + 4];
#pragma unroll
            for (int nt = 0; nt < 8; nt++) {
                uint32_t b0 = bu[(nt * 8 + g) * GST + kt * 8 + t];
                uint32_t b1 = bu[(nt * 8 + g) * GST + kt * 8 + t + 4];
                mma8(c[nt], a0, a1, a2, a3, b0, b1);
            }
        }
        __syncthreads();
    }

    int tsel = o0 / CDIM;
    int h = (o0 % CDIM) >> 6;
    float* dst = (tsel == 0) ? g_q : ((tsel == 1) ? g_k : g_v);
    dst += (size_t)((b * NHEAD + h) * NTOK) * HDIM;
    int gr0 = m0 + r0, gr1 = m0 + r0 + 8;
#pragma unroll
    for (int nt = 0; nt < 8; nt++) {
        int col = nt * 8 + 2 * t;
        if (gr0 < NTOK)
            *(float2*)&dst[(size_t)gr0 * HDIM + col] =
                make_float2(to_tf32(c[nt][0]), to_tf32(c[nt][1]));
        if (gr1 < NTOK)
            *(float2*)&dst[(size_t)gr1 * HDIM + col] =
                make_float2(to_tf32(c[nt][2]), to_tf32(c[nt][3]));
    }
}

// ---------------- output projection GEMM (tf32 TC, cp.async) ----------------
__global__ __launch_bounds__(128) void proj_tc(const float* __restrict__ src,
                                               const float* __restrict__ W,
                                               const float* __restrict__ bias,
                                               float* __restrict__ out,
                                               float prescale) {
    __shared__ float As[2][64 * GST];
    __shared__ float Bs[2][64 * GST];
    int tid = threadIdx.x;
    int warp = tid >> 5, lane = tid & 31;
    int g = lane >> 2, t = lane & 3;
    int m0 = blockIdx.x * 64;
    int o0 = blockIdx.y * 64;
    int b = blockIdx.z;
    const int r0 = warp * 16 + g;

    float c[8][4];
#pragma unroll
    for (int nt = 0; nt < 8; nt++)
#pragma unroll
        for (int j = 0; j < 4; j++) c[nt][j] = 0.f;

    // issue tile 0 (c0 = 0 -> h = 0, dlo = 0)
#pragma unroll
    for (int e = 0; e < 4; e++) {
        int idx = tid + e * 128;
        int row = idx >> 3;
        int cs = (idx & 7) << 2;
        bool p = (m0 + row) < NTOK;
        int rr = p ? (m0 + row) : (NTOK - 1);
        cp16(smem_u32(&As[0][row * GST + cs]),
             src + (size_t)((b * NHEAD + 0) * NTOK + rr) * HDIM + cs, p);
        cp16(smem_u32(&Bs[0][row * GST + cs]),
             W + (size_t)(o0 + row) * CDIM + cs, true);
    }
    cp_commit();

    for (int i = 0; i < KTILES; i++) {
        int cur = i & 1;
        if (i + 1 < KTILES) {
            int c0 = (i + 1) * 32;
            int h = c0 >> 6;
            int dlo = c0 & 63;
#pragma unroll
            for (int e = 0; e < 4; e++) {
                int idx = tid + e * 128;
                int row = idx >> 3;
                int cs = (idx & 7) << 2;
                bool p = (m0 + row) < NTOK;
                int rr = p ? (m0 + row) : (NTOK - 1);
                cp16(smem_u32(&As[1 - cur][row * GST + cs]),
                     src + (size_t)((b * NHEAD + h) * NTOK + rr) * HDIM + dlo + cs, p);
                cp16(smem_u32(&Bs[1 - cur][row * GST + cs]),
                     W + (size_t)(o0 + row) * CDIM + c0 + cs, true);
            }
            cp_commit();
            cp_wait1();
        } else {
            cp_wait0();
        }
        __syncthreads();

        const uint32_t* au = (const uint32_t*)As[cur];
        const uint32_t* bu = (const uint32_t*)Bs[cur];
#pragma unroll
        for (int kt = 0; kt < 4; kt++) {
            uint32_t a0 = au[r0 * GST + kt * 8 + t];
            uint32_t a1 = au[(r0 + 8) * GST + kt * 8 + t];
            uint32_t a2 = au[r0 * GST + kt * 8 + t + 4];
            uint32_t a3 = au[(r0 + 8) * GST + kt * 8 + t + 4];
#pragma unroll
            for (int nt = 0; nt < 8; nt++) {
                uint32_t b0 = bu[(nt * 8 + g) * GST + kt * 8 + t];
                uint32_t b1 = bu[(nt * 8 + g) * GST + kt * 8 + t + 4];
                mma8(c[nt], a0, a1, a2, a3, b0, b1);
            }
        }
        __syncthreads();
    }

    int gr0 = m0 + r0, gr1 = m0 + r0 + 8;
#pragma unroll
    for (int nt = 0; nt < 8; nt++) {
        int col = nt * 8 + 2 * t;
        float b0 = bias[o0 + col], b1 = bias[o0 + col + 1];
        if (gr0 < NTOK)
            *(float2*)(out + (size_t)gr0 * (BATCH * CDIM) + b * CDIM + o0 + col) =
                make_float2(c[nt][0] * prescale + b0, c[nt][1] * prescale + b1);
        if (gr1 < NTOK)
            *(float2*)(out + (size_t)gr1 * (BATCH * CDIM) + b * CDIM + o0 + col) =
                make_float2(c[nt][2] * prescale + b0, c[nt][3] * prescale + b1);
    }
}

// ---------------- host orchestration ---------------------------------------
extern "C" void kernel_launch(void* const* d_in, const int* in_sizes, int n_in,
                              void* d_out, int out_size) {
    const float* x = (const float*)d_in[0];
    const float* Wqkv = (const float*)d_in[1];
    const float* Wproj = (const float*)d_in[2];
    const float* bproj = (const float*)d_in[3];
    float* out = (float*)d_out;

    cudaFuncSetAttribute(attn_tc, cudaFuncAttributeMaxDynamicSharedMemorySize,
                         ATT_SMEM);

    float *q, *k, *v, *xs, *t1, *accb, *xr, *wq, *wp;
    cudaGetSymbolAddress((void**)&q, g_q);
    cudaGetSymbolAddress((void**)&k, g_k);
    cudaGetSymbolAddress((void**)&v, g_v);
    cudaGetSymbolAddress((void**)&xs, g_xs);
    cudaGetSymbolAddress((void**)&t1, g_t1);
    cudaGetSymbolAddress((void**)&accb, g_acc);
    cudaGetSymbolAddress((void**)&xr, g_xr);
    cudaGetSymbolAddress((void**)&wq, g_wq);
    cudaGetSymbolAddress((void**)&wp, g_wp);

    const int LN_GRID = (BH * NTOK * 32 + 255) / 256;
    const int ADD_GRID = (BHND / 4 + 255) / 256;
    dim3 ga((NTOK + 127) / 128, BH);       // 13 x 96
    dim3 gq((NTOK + 63) / 64, 36, BATCH);
    dim3 gp((NTOK + 63) / 64, 12, BATCH);

    // prep: tf32-round inputs/weights once
    round_kernel<<<(NBC / 4 + 255) / 256, 256>>>(x, xr, NBC / 4);
    round_kernel<<<(3 * CDIM * CDIM / 4 + 255) / 256, 256>>>(Wqkv, wq, 3 * CDIM * CDIM / 4);
    round_kernel<<<(CDIM * CDIM / 4 + 255) / 256, 256>>>(Wproj, wp, CDIM * CDIM / 4);

    rownorm_kernel<<<(BATCH * NTOK * 32 + 255) / 256, 256>>>(x);
    invtemp_kernel<<<BATCH, 256>>>();

    qkv_tc<<<gq, 128>>>(xr, wq);

    // original attention -> x_ori (second half of output)
    attn_tc<<<ga, 128, ATT_SMEM>>>(q, k, v, t1, 0, 0.125f, 1);
    proj_tc<<<gp, 128>>>(t1, wp, bproj, out + NBC, 1.0f);

    // branch(v)
    l2norm_kernel<<<LN_GRID, 256>>>(v, xs);
    attn_tc<<<ga, 128, ATT_SMEM>>>(xs, xs, xs, t1, 1, 0.f, 1);
    l2norm_kernel<<<LN_GRID, 256>>>(t1, xs);
    attn_tc<<<ga, 128, ATT_SMEM>>>(xs, xs, v, accb, 1, 0.f, 1);

    // branch(k)
    l2norm_kernel<<<LN_GRID, 256>>>(k, xs);
    attn_tc<<<ga, 128, ATT_SMEM>>>(xs, xs, xs, t1, 1, 0.f, 1);
    l2norm_kernel<<<LN_GRID, 256>>>(t1, xs);
    attn_tc<<<ga, 128, ATT_SMEM>>>(xs, xs, v, t1, 1, 0.f, 1);
    add_kernel<<<ADD_GRID, 256>>>(accb, t1);

    // branch(q)
    l2norm_kernel<<<LN_GRID, 256>>>(q, xs);
    attn_tc<<<ga, 128, ATT_SMEM>>>(xs, xs, xs, t1, 1, 0.f, 1);
    l2norm_kernel<<<LN_GRID, 256>>>(t1, xs);
    attn_tc<<<ga, 128, ATT_SMEM>>>(xs, xs, v, t1, 1, 0.f, 1);
    add_kernel<<<ADD_GRID, 256>>>(accb, t1);

    proj_tc<<<gp, 128>>>(accb, wp, bproj, out, 1.0f / 3.0f);
}

// round 13
// speedup vs baseline: 1.0746x; 1.0746x over previous
#include <cuda_runtime.h>
#include <math.h>
#include <stdint.h>

#define NTOK 1569
#define BATCH 8
#define CDIM 768
#define NHEAD 12
#define HDIM 64
#define BH (BATCH*NHEAD)            /* 96 */
#define BHND (BH*NTOK*HDIM)         /* 9639936 */
#define NBC (NTOK*BATCH*CDIM)       /* 9639936 */

// ---------------- scratch (device globals: no allocation allowed) ----------
__device__ float g_q[BHND];
__device__ float g_k[BHND];
__device__ float g_v[BHND];
__device__ float g_xs[3*BHND];          // batched l2norm outputs
__device__ float g_t1[BHND];            // ori attention output
__device__ float g_t2[3*BHND];          // batched branch outputs
__device__ float g_rownorm[BATCH*NTOK];
__device__ float g_invtemp[BATCH];

// ---------------- tf32 helpers ---------------------------------------------
__device__ __forceinline__ float to_tf32(float x) {
    uint32_t u;
    asm("cvt.rna.tf32.f32 %0, %1;" : "=r"(u) : "f"(x));
    return __uint_as_float(u);
}

__device__ __forceinline__ float ex2(float x) {
    float r;
    asm("ex2.approx.f32 %0, %1;" : "=f"(r) : "f"(x));
    return r;
}

__device__ __forceinline__ void mma8(float* c, uint32_t a0, uint32_t a1,
                                     uint32_t a2, uint32_t a3,
                                     uint32_t b0, uint32_t b1) {
    asm volatile(
        "mma.sync.aligned.m16n8k8.row.col.f32.tf32.tf32.f32 "
        "{%0,%1,%2,%3}, {%4,%5,%6,%7}, {%8,%9}, {%0,%1,%2,%3};"
        : "+f"(c[0]), "+f"(c[1]), "+f"(c[2]), "+f"(c[3])
        : "r"(a0), "r"(a1), "r"(a2), "r"(a3), "r"(b0), "r"(b1));
}

// ---------------- per-token L2 norm over C (for inv_temp) ------------------
__global__ void rownorm_kernel(const float* __restrict__ x) {
    int r = (blockIdx.x * blockDim.x + threadIdx.x) >> 5;
    int lane = threadIdx.x & 31;
    if (r >= BATCH * NTOK) return;
    int b = r / NTOK, n = r - b * NTOK;
    const float* p = x + (size_t)n * (BATCH * CDIM) + b * CDIM;
    float ss = 0.f;
#pragma unroll
    for (int kblk = 0; kblk < 6; kblk++) {
        float4 v = *(const float4*)(p + kblk * 128 + lane * 4);
        ss += v.x * v.x + v.y * v.y + v.z * v.z + v.w * v.w;
    }
#pragma unroll
    for (int o = 16; o; o >>= 1) ss += __shfl_xor_sync(0xffffffffu, ss, o);
    if (lane == 0) g_rownorm[r] = sqrtf(ss);
}

__global__ void invtemp_kernel() {
    __shared__ float sh[256];
    int b = blockIdx.x;
    float s = 0.f;
    for (int n = threadIdx.x; n < NTOK; n += 256) s += g_rownorm[b * NTOK + n];
    sh[threadIdx.x] = s;
    __syncthreads();
    for (int o = 128; o; o >>= 1) {
        if (threadIdx.x < o) sh[threadIdx.x] += sh[threadIdx.x + o];
        __syncthreads();
    }
    if (threadIdx.x == 0) g_invtemp[b] = (sh[0] / (float)NTOK) * 0.125f;
}

// ---------------- batched l2 normalize (3 sources -> contiguous out) --------
__global__ void l2norm3_kernel(const float* __restrict__ p0,
                               const float* __restrict__ p1,
                               const float* __restrict__ p2,
                               float* __restrict__ out) {
    int r = (blockIdx.x * blockDim.x + threadIdx.x) >> 5;
    int lane = threadIdx.x & 31;
    if (r >= 3 * BH * NTOK) return;
    int z = r / (BH * NTOK);
    int rr = r - z * (BH * NTOK);
    const float* in = (z == 0) ? p0 : ((z == 1) ? p1 : p2);
    float2 v = *(const float2*)(in + (size_t)rr * HDIM + lane * 2);
    float ss = v.x * v.x + v.y * v.y;
#pragma unroll
    for (int o = 16; o; o >>= 1) ss += __shfl_xor_sync(0xffffffffu, ss, o);
    float inv = 1.f / fmaxf(sqrtf(ss), 1e-12f);
    *(float2*)(out + (size_t)r * HDIM + lane * 2) = make_float2(v.x * inv, v.y * inv);
}

// ---------------- flash attention (tf32 tensor-core, M=32/warp) -------------
// Identical math to the R6 kernel; adds z-strides so one launch can cover the
// three independent ss-branches via gridDim.z.
#define AST 68
#define VST 72
#define ATT_SMEM ((128*AST + 64*AST + 64*VST) * 4)

__global__ __launch_bounds__(128) void attn_tc(
    const float* __restrict__ Q, const float* __restrict__ K,
    const float* __restrict__ V, float* __restrict__ O,
    int useInvTemp, float cscale, int zsQ, int zsV) {
    extern __shared__ float sm[];
    float* Ps = sm;                       // 128 x AST: Q staging, then P
    float* Ks = sm + 128 * AST;           // 64 x AST
    float* Vs = sm + 128 * AST + 64 * AST;// 64 x VST

    size_t zq = (size_t)blockIdx.z * zsQ;
    Q += zq; K += zq; O += zq;
    V += (size_t)blockIdx.z * zsV;

    int tid = threadIdx.x;
    int warp = tid >> 5, lane = tid & 31;
    int g = lane >> 2, t = lane & 3;
    int bh = blockIdx.y;
    int m0 = blockIdx.x * 128;
    float scale = useInvTemp ? g_invtemp[bh / NHEAD] : cscale;
    const float qscale = scale * 1.4426950408889634f;  // fold log2(e) for ex2
    const size_t base = (size_t)bh * NTOK * HDIM;
    const int rA = warp * 32 + g;
    const int rB = warp * 32 + 16 + g;

    // ---- stage Q (scaled, tf32) into Ps ----
#pragma unroll
    for (int e = 0; e < 16; e++) {
        int idx = tid + e * 128;
        int row = idx >> 4;
        int d = (idx & 15) << 2;
        float4 qv = make_float4(0.f, 0.f, 0.f, 0.f);
        if (m0 + row < NTOK)
            qv = *(const float4*)(Q + base + (size_t)(m0 + row) * HDIM + d);
        float4 w;
        w.x = to_tf32(qv.x * qscale); w.y = to_tf32(qv.y * qscale);
        w.z = to_tf32(qv.z * qscale); w.w = to_tf32(qv.w * qscale);
        *(float4*)&Ps[row * AST + d] = w;
    }
    __syncthreads();

    // ---- hoist Q fragments for both m-blocks into registers ----
    uint32_t qA[8][4], qB[8][4];
    {
        const uint32_t* pu = (const uint32_t*)Ps;
#pragma unroll
        for (int kt = 0; kt < 8; kt++) {
            qA[kt][0] = pu[rA * AST + kt * 8 + t];
            qA[kt][1] = pu[(rA + 8) * AST + kt * 8 + t];
            qA[kt][2] = pu[rA * AST + kt * 8 + t + 4];
            qA[kt][3] = pu[(rA + 8) * AST + kt * 8 + t + 4];
            qB[kt][0] = pu[rB * AST + kt * 8 + t];
            qB[kt][1] = pu[(rB + 8) * AST + kt * 8 + t];
            qB[kt][2] = pu[rB * AST + kt * 8 + t + 4];
            qB[kt][3] = pu[(rB + 8) * AST + kt * 8 + t + 4];
        }
    }

    float lA0 = 0.f, lA1 = 0.f, lB0 = 0.f, lB1 = 0.f;
    float oA[8][4], oB[8][4];
#pragma unroll
    for (int nt = 0; nt < 8; nt++)
#pragma unroll
        for (int j = 0; j < 4; j++) { oA[nt][j] = 0.f; oB[nt][j] = 0.f; }

    for (int kt0 = 0; kt0 < NTOK; kt0 += 64) {
        __syncthreads();
#pragma unroll
        for (int e = 0; e < 8; e++) {
            int idx = tid + e * 128;
            int row = idx >> 4;
            int d = (idx & 15) << 2;
            float4 kv = make_float4(0.f, 0.f, 0.f, 0.f);
            float4 vv = make_float4(0.f, 0.f, 0.f, 0.f);
            if (kt0 + row < NTOK) {
                kv = *(const float4*)(K + base + (size_t)(kt0 + row) * HDIM + d);
                vv = *(const float4*)(V + base + (size_t)(kt0 + row) * HDIM + d);
            }
            float4 kw, vw;
            kw.x = to_tf32(kv.x); kw.y = to_tf32(kv.y);
            kw.z = to_tf32(kv.z); kw.w = to_tf32(kv.w);
            vw.x = to_tf32(vv.x); vw.y = to_tf32(vv.y);
            vw.z = to_tf32(vv.z); vw.w = to_tf32(vv.w);
            *(float4*)&Ks[row * AST + d] = kw;
            *(float4*)&Vs[row * VST + d] = vw;
        }
        __syncthreads();

        // ---- S = (Q*qscale) K^T  (both m-blocks share B fragments) ----
        float sA[8][4], sB[8][4];
#pragma unroll
        for (int nt = 0; nt < 8; nt++)
#pragma unroll
            for (int j = 0; j < 4; j++) { sA[nt][j] = 0.f; sB[nt][j] = 0.f; }

        const uint32_t* ku = (const uint32_t*)Ks;
#pragma unroll
        for (int kt = 0; kt < 8; kt++) {
#pragma unroll
            for (int nt = 0; nt < 8; nt++) {
                uint32_t b0 = ku[(nt * 8 + g) * AST + kt * 8 + t];
                uint32_t b1 = ku[(nt * 8 + g) * AST + kt * 8 + t + 4];
                mma8(sA[nt], qA[kt][0], qA[kt][1], qA[kt][2], qA[kt][3], b0, b1);
                mma8(sB[nt], qB[kt][0], qB[kt][1], qB[kt][2], qB[kt][3], b0, b1);
            }
        }

        // ---- no-max softmax: p = 2^s ----
        bool tail = (kt0 + 64 > NTOK);
#pragma unroll
        for (int nt = 0; nt < 8; nt++) {
            if (tail) {
                int cg = kt0 + nt * 8 + 2 * t;
                if (cg >= NTOK) {
                    sA[nt][0] = -1e30f; sA[nt][2] = -1e30f;
                    sB[nt][0] = -1e30f; sB[nt][2] = -1e30f;
                }
                if (cg + 1 >= NTOK) {
                    sA[nt][1] = -1e30f; sA[nt][3] = -1e30f;
                    sB[nt][1] = -1e30f; sB[nt][3] = -1e30f;
                }
            }
            float pA0 = ex2(sA[nt][0]);
            float pA1 = ex2(sA[nt][1]);
            float pA2 = ex2(sA[nt][2]);
            float pA3 = ex2(sA[nt][3]);
            float pB0 = ex2(sB[nt][0]);
            float pB1 = ex2(sB[nt][1]);
            float pB2 = ex2(sB[nt][2]);
            float pB3 = ex2(sB[nt][3]);
            lA0 += pA0 + pA1; lA1 += pA2 + pA3;
            lB0 += pB0 + pB1; lB1 += pB2 + pB3;
            int col = nt * 8 + 2 * t;
            *(float2*)&Ps[rA * AST + col]       = make_float2(to_tf32(pA0), to_tf32(pA1));
            *(float2*)&Ps[(rA + 8) * AST + col] = make_float2(to_tf32(pA2), to_tf32(pA3));
            *(float2*)&Ps[rB * AST + col]       = make_float2(to_tf32(pB0), to_tf32(pB1));
            *(float2*)&Ps[(rB + 8) * AST + col] = make_float2(to_tf32(pB2), to_tf32(pB3));
        }
        __syncwarp();

        // ---- O += P V  (both m-blocks share B fragments) ----
        const uint32_t* pu = (const uint32_t*)Ps;
        const uint32_t* vu = (const uint32_t*)Vs;
#pragma unroll
        for (int kt = 0; kt < 8; kt++) {
            uint32_t aA0 = pu[rA * AST + kt * 8 + t];
            uint32_t aA1 = pu[(rA + 8) * AST + kt * 8 + t];
            uint32_t aA2 = pu[rA * AST + kt * 8 + t + 4];
            uint32_t aA3 = pu[(rA + 8) * AST + kt * 8 + t + 4];
            uint32_t aB0 = pu[rB * AST + kt * 8 + t];
            uint32_t aB1 = pu[(rB + 8) * AST + kt * 8 + t];
            uint32_t aB2 = pu[rB * AST + kt * 8 + t + 4];
            uint32_t aB3 = pu[(rB + 8) * AST + kt * 8 + t + 4];
#pragma unroll
            for (int nt = 0; nt < 8; nt++) {
                uint32_t b0 = vu[(kt * 8 + t) * VST + nt * 8 + g];
                uint32_t b1 = vu[(kt * 8 + t + 4) * VST + nt * 8 + g];
                mma8(oA[nt], aA0, aA1, aA2, aA3, b0, b1);
                mma8(oB[nt], aB0, aB1, aB2, aB3, b0, b1);
            }
        }
    }

    // deferred l reduction over the 4 t-lanes of each row group
    lA0 += __shfl_xor_sync(0xffffffffu, lA0, 1);
    lA0 += __shfl_xor_sync(0xffffffffu, lA0, 2);
    lA1 += __shfl_xor_sync(0xffffffffu, lA1, 1);
    lA1 += __shfl_xor_sync(0xffffffffu, lA1, 2);
    lB0 += __shfl_xor_sync(0xffffffffu, lB0, 1);
    lB0 += __shfl_xor_sync(0xffffffffu, lB0, 2);
    lB1 += __shfl_xor_sync(0xffffffffu, lB1, 1);
    lB1 += __shfl_xor_sync(0xffffffffu, lB1, 2);
    float iA0 = 1.f / lA0, iA1 = 1.f / lA1, iB0 = 1.f / lB0, iB1 = 1.f / lB1;
#pragma unroll
    for (int nt = 0; nt < 8; nt++) {
        int col = nt * 8 + 2 * t;
        int r;
        r = m0 + rA;
        if (r < NTOK)
            *(float2*)(O + base + (size_t)r * HDIM + col) =
                make_float2(oA[nt][0] * iA0, oA[nt][1] * iA0);
        r = m0 + rA + 8;
        if (r < NTOK)
            *(float2*)(O + base + (size_t)r * HDIM + col) =
                make_float2(oA[nt][2] * iA1, oA[nt][3] * iA1);
        r = m0 + rB;
        if (r < NTOK)
            *(float2*)(O + base + (size_t)r * HDIM + col) =
                make_float2(oB[nt][0] * iB0, oB[nt][1] * iB0);
        r = m0 + rB + 8;
        if (r < NTOK)
            *(float2*)(O + base + (size_t)r * HDIM + col) =
                make_float2(oB[nt][2] * iB1, oB[nt][3] * iB1);
    }
}

// ---------------- qkv projection GEMM (tf32 tensor-core) --------------------
#define GST 36

__global__ __launch_bounds__(128) void qkv_tc(const float* __restrict__ x,
                                              const float* __restrict__ W) {
    __shared__ float As[64 * GST];
    __shared__ float Bs[64 * GST];
    int tid = threadIdx.x;
    int warp = tid >> 5, lane = tid & 31;
    int g = lane >> 2, t = lane & 3;
    int m0 = blockIdx.x * 64;
    int o0 = blockIdx.y * 64;
    int b = blockIdx.z;
    const int r0 = warp * 16 + g;

    float c[8][4];
#pragma unroll
    for (int nt = 0; nt < 8; nt++)
#pragma unroll
        for (int j = 0; j < 4; j++) c[nt][j] = 0.f;

    for (int c0 = 0; c0 < CDIM; c0 += 32) {
        __syncthreads();
#pragma unroll
        for (int e = 0; e < 4; e++) {
            int idx = tid + e * 128;
            int row = idx >> 3;
            int cs = (idx & 7) << 2;
            float4 a4 = make_float4(0.f, 0.f, 0.f, 0.f);
            if (m0 + row < NTOK)
                a4 = *(const float4*)(x + (size_t)(m0 + row) * (BATCH * CDIM) + b * CDIM + c0 + cs);
            float4 aw;
            aw.x = to_tf32(a4.x); aw.y = to_tf32(a4.y);
            aw.z = to_tf32(a4.z); aw.w = to_tf32(a4.w);
            *(float4*)&As[row * GST + cs] = aw;
            float4 b4 = *(const float4*)(W + (size_t)(o0 + row) * CDIM + c0 + cs);
            float4 bw;
            bw.x = to_tf32(b4.x); bw.y = to_tf32(b4.y);
            bw.z = to_tf32(b4.z); bw.w = to_tf32(b4.w);
            *(float4*)&Bs[row * GST + cs] = bw;
        }
        __syncthreads();

        const uint32_t* au = (const uint32_t*)As;
        const uint32_t* bu = (const uint32_t*)Bs;
#pragma unroll
        for (int kt = 0; kt < 4; kt++) {
            uint32_t a0 = au[r0 * GST + kt * 8 + t];
            uint32_t a1 = au[(r0 + 8) * GST + kt * 8 + t];
            uint32_t a2 = au[r0 * GST + kt * 8 + t + 4];
            uint32_t a3 = au[(r0 + 8) * GST + kt * 8 + t + 4];
#pragma unroll
            for (int nt = 0; nt < 8; nt++) {
                uint32_t b0 = bu[(nt * 8 + g) * GST + kt * 8 + t];
                uint32_t b1 = bu[(nt * 8 + g) * GST + kt * 8 + t + 4];
                mma8(c[nt], a0, a1, a2, a3, b0, b1);
            }
        }
    }

    int tsel = o0 / CDIM;
    int h = (o0 % CDIM) >> 6;
    float* dst = (tsel == 0) ? g_q : ((tsel == 1) ? g_k : g_v);
    dst += (size_t)((b * NHEAD + h) * NTOK) * HDIM;
    int gr0 = m0 + r0, gr1 = m0 + r0 + 8;
#pragma unroll
    for (int nt = 0; nt < 8; nt++) {
        int col = nt * 8 + 2 * t;
        if (gr0 < NTOK)
            *(float2*)&dst[(size_t)gr0 * HDIM + col] = make_float2(c[nt][0], c[nt][1]);
        if (gr1 < NTOK)
            *(float2*)&dst[(size_t)gr1 * HDIM + col] = make_float2(c[nt][2], c[nt][3]);
    }
}

// ---------------- output projection GEMM (tf32 TC; optional 3-way sum) ------
// If s1/s2 non-null: A-tile = s0+s1+s2 (fp32 adds, then one tf32 round).
__global__ __launch_bounds__(128) void proj_tc(const float* __restrict__ s0,
                                               const float* __restrict__ s1,
                                               const float* __restrict__ s2,
                                               const float* __restrict__ W,
                                               const float* __restrict__ bias,
                                               float* __restrict__ out,
                                               float prescale) {
    __shared__ float As[64 * GST];
    __shared__ float Bs[64 * GST];
    int tid = threadIdx.x;
    int warp = tid >> 5, lane = tid & 31;
    int g = lane >> 2, t = lane & 3;
    int m0 = blockIdx.x * 64;
    int o0 = blockIdx.y * 64;
    int b = blockIdx.z;
    const int r0 = warp * 16 + g;

    float c[8][4];
#pragma unroll
    for (int nt = 0; nt < 8; nt++)
#pragma unroll
        for (int j = 0; j < 4; j++) c[nt][j] = 0.f;

    for (int c0 = 0; c0 < CDIM; c0 += 32) {
        int h = c0 >> 6;
        int dlo = c0 & 63;
        __syncthreads();
#pragma unroll
        for (int e = 0; e < 4; e++) {
            int idx = tid + e * 128;
            int row = idx >> 3;
            int cs = (idx & 7) << 2;
            float4 a4 = make_float4(0.f, 0.f, 0.f, 0.f);
            if (m0 + row < NTOK) {
                size_t off = (size_t)((b * NHEAD + h) * NTOK + m0 + row) * HDIM + dlo + cs;
                a4 = *(const float4*)(s0 + off);
                if (s1) {
                    float4 a1 = *(const float4*)(s1 + off);
                    float4 a2 = *(const float4*)(s2 + off);
                    a4.x += a1.x + a2.x; a4.y += a1.y + a2.y;
                    a4.z += a1.z + a2.z; a4.w += a1.w + a2.w;
                }
            }
            float4 aw;
            aw.x = to_tf32(a4.x); aw.y = to_tf32(a4.y);
            aw.z = to_tf32(a4.z); aw.w = to_tf32(a4.w);
            *(float4*)&As[row * GST + cs] = aw;
            float4 b4 = *(const float4*)(W + (size_t)(o0 + row) * CDIM + c0 + cs);
            float4 bw;
            bw.x = to_tf32(b4.x); bw.y = to_tf32(b4.y);
            bw.z = to_tf32(b4.z); bw.w = to_tf32(b4.w);
            *(float4*)&Bs[row * GST + cs] = bw;
        }
        __syncthreads();

        const uint32_t* au = (const uint32_t*)As;
        const uint32_t* bu = (const uint32_t*)Bs;
#pragma unroll
        for (int kt = 0; kt < 4; kt++) {
            uint32_t a0 = au[r0 * GST + kt * 8 + t];
            uint32_t a1 = au[(r0 + 8) * GST + kt * 8 + t];
            uint32_t a2 = au[r0 * GST + kt * 8 + t + 4];
            uint32_t a3 = au[(r0 + 8) * GST + kt * 8 + t + 4];
#pragma unroll
            for (int nt = 0; nt < 8; nt++) {
                uint32_t b0 = bu[(nt * 8 + g) * GST + kt * 8 + t];
                uint32_t b1 = bu[(nt * 8 + g) * GST + kt * 8 + t + 4];
                mma8(c[nt], a0, a1, a2, a3, b0, b1);
            }
        }
    }

    int gr0 = m0 + r0, gr1 = m0 + r0 + 8;
#pragma unroll
    for (int nt = 0; nt < 8; nt++) {
        int col = nt * 8 + 2 * t;
        float b0 = bias[o0 + col], b1 = bias[o0 + col + 1];
        if (gr0 < NTOK)
            *(float2*)(out + (size_t)gr0 * (BATCH * CDIM) + b * CDIM + o0 + col) =
                make_float2(c[nt][0] * prescale + b0, c[nt][1] * prescale + b1);
        if (gr1 < NTOK)
            *(float2*)(out + (size_t)gr1 * (BATCH * CDIM) + b * CDIM + o0 + col) =
                make_float2(c[nt][2] * prescale + b0, c[nt][3] * prescale + b1);
    }
}

// ---------------- host orchestration ---------------------------------------
extern "C" void kernel_launch(void* const* d_in, const int* in_sizes, int n_in,
                              void* d_out, int out_size) {
    const float* x = (const float*)d_in[0];
    const float* Wqkv = (const float*)d_in[1];
    const float* Wproj = (const float*)d_in[2];
    const float* bproj = (const float*)d_in[3];
    float* out = (float*)d_out;

    cudaFuncSetAttribute(attn_tc, cudaFuncAttributeMaxDynamicSharedMemorySize,
                         ATT_SMEM);

    float *q, *k, *v, *xs, *t1, *t2;
    cudaGetSymbolAddress((void**)&q, g_q);
    cudaGetSymbolAddress((void**)&k, g_k);
    cudaGetSymbolAddress((void**)&v, g_v);
    cudaGetSymbolAddress((void**)&xs, g_xs);
    cudaGetSymbolAddress((void**)&t1, g_t1);
    cudaGetSymbolAddress((void**)&t2, g_t2);

    const int LN3_GRID = (3 * BH * NTOK * 32 + 255) / 256;
    dim3 ga((NTOK + 127) / 128, BH, 1);    // 13 x 96 (ori)
    dim3 gab((NTOK + 127) / 128, BH, 3);   // 13 x 96 x 3 (batched branches)
    dim3 gq((NTOK + 63) / 64, 36, BATCH);
    dim3 gp((NTOK + 63) / 64, 12, BATCH);

    rownorm_kernel<<<(BATCH * NTOK * 32 + 255) / 256, 256>>>(x);
    invtemp_kernel<<<BATCH, 256>>>();

    qkv_tc<<<gq, 128>>>(x, Wqkv);

    // original attention -> x_ori (second half of output)
    attn_tc<<<ga, 128, ATT_SMEM>>>(q, k, v, t1, 0, 0.125f, 0, 0);
    proj_tc<<<gp, 128>>>(t1, nullptr, nullptr, Wproj, bproj, out + NBC, 1.0f);

    // batched branches: z=0 -> v, z=1 -> k, z=2 -> q
    l2norm3_kernel<<<LN3_GRID, 256>>>(v, k, q, xs);
    attn_tc<<<gab, 128, ATT_SMEM>>>(xs, xs, xs, t2, 1, 0.f, BHND, BHND);
    l2norm3_kernel<<<LN3_GRID, 256>>>(t2, t2 + BHND, t2 + 2 * BHND, xs);
    attn_tc<<<gab, 128, ATT_SMEM>>>(xs, xs, v, t2, 1, 0.f, BHND, 0);

    // x_out = ((b_v + b_k + b_q)/3) @ Wproj^T + bproj  (first half of output)
    proj_tc<<<gp, 128>>>(t2, t2 + BHND, t2 + 2 * BHND, Wproj, bproj, out,
                         1.0f / 3.0f);
}